// round 1
// baseline (speedup 1.0000x reference)
#include <cuda_runtime.h>

#define EPSF 1e-5f

// ---------------- scratch (static device globals; no allocation) ----------------
__device__ float g_h[(size_t)4 * 21504 * 512];      // region GEMM out / activated in-place
__device__ float g_y[(size_t)12 * 21504 * 512];     // class GEMM out (pre-BN)
__device__ float g_hmean[(size_t)4 * 1024 * 512];   // seq-mean of activated h
__device__ float g_fv[(size_t)1024 * 12 * 512];     // f_v
__device__ float g_hg[(size_t)1024 * 12 * 512];     // GAT projection
__device__ float g_gat[(size_t)1024 * 12 * 512];    // GAT output (g)
__device__ float g_v[(size_t)1024 * 12 * 512];      // temporal conv out (pre-BN)
__device__ float g_rstats[4 * 512 * 2];             // region BN sum/sumsq
__device__ float g_cstats[12 * 512 * 2];            // class BN sum/sumsq
__device__ float g_tstats[24];                      // temporal BN sum/sumsq per class

__constant__ int c_sel[12]  = {0, 0, 0, 1, 0, 3, 2, 2, 2, 3, 3, 3};
__constant__ int c_start[4] = {0, 14, 28, 28};
__constant__ float c_adj[144] = {
    0,0,0,1,0,1,1,1,1,1,1,1,
    0,0,0,1,0,1,1,1,1,1,1,1,
    0,0,0,1,0,1,1,1,1,1,1,1,
    1,1,1,0,1,1,1,1,1,1,1,1,
    0,0,0,1,0,1,1,1,1,1,1,1,
    1,1,1,1,1,0,1,1,1,0,0,0,
    1,1,1,1,1,1,0,0,0,1,1,1,
    1,1,1,1,1,1,0,0,0,1,1,1,
    1,1,1,1,1,1,0,0,0,1,1,1,
    1,1,1,1,1,0,1,1,1,0,0,0,
    1,1,1,1,1,0,1,1,1,0,0,0,
    1,1,1,1,1,0,1,1,1,0,0,0
};

// ---------------- stats zeroing ----------------
__global__ void zero_stats_kernel() {
    int i = blockIdx.x * blockDim.x + threadIdx.x;
    if (i < 4 * 512 * 2)  g_rstats[i] = 0.f;
    if (i < 12 * 512 * 2) g_cstats[i] = 0.f;
    if (i < 24)           g_tstats[i] = 0.f;
}

// ---------------- 128x128x8 fp32 GEMM, bias + fused BN-statistics epilogue ----------------
// mode 0: region   A = x  (grid of 49 positions, region slice per z), Y = g_h,  stats = g_rstats
// mode 1: class    A = g_h[sel[z]],                                  Y = g_y,  stats = g_cstats
// mode 2: gat      A = g_fv (plain rows),                            Y = g_hg, no stats
__global__ __launch_bounds__(256)
void gemm_k(const float* __restrict__ A_ext,
            const float* __restrict__ W,
            const float* __restrict__ bias,
            int M, int mode)
{
    __shared__ float As[8][132];   // padded to kill store conflicts, float4-aligned
    __shared__ float Bs[8][128];
    __shared__ float cstat[256];

    const float* A;
    float* Y;
    float* stats;
    if (mode == 0)      { A = A_ext; Y = g_h;  stats = g_rstats; }
    else if (mode == 1) { A = g_h;   Y = g_y;  stats = g_cstats; }
    else                { A = g_fv;  Y = g_hg; stats = nullptr;  }

    const int z   = blockIdx.z;
    const int n0  = blockIdx.x * 128;
    const int m0  = blockIdx.y * 128;
    const int tid = threadIdx.x;

    // A tile loader mapping: thread -> (row in tile, half of 8-wide k strip)
    const int lrow = tid >> 1;
    const int ka   = (tid & 1) * 4;
    const int m    = m0 + lrow;
    const float* arow;
    if (mode == 0) {
        int bt = m / 21;
        int s  = m - bt * 21;
        arow = A + ((size_t)bt * 49 + c_start[z] + s) * 512 + ka;
    } else if (mode == 1) {
        arow = A + ((size_t)c_sel[z] * M + m) * 512 + ka;
    } else {
        arow = A + (size_t)m * 512 + ka;
    }
    // B tile loader mapping
    const int bk = tid >> 5;
    const int bc = (tid & 31) * 4;
    const float* wrow = W + (size_t)z * 512 * 512 + (size_t)bk * 512 + n0 + bc;

    const int tx = tid & 15;
    const int ty = tid >> 4;

    float acc[8][8];
    #pragma unroll
    for (int i = 0; i < 8; ++i)
        #pragma unroll
        for (int j = 0; j < 8; ++j) acc[i][j] = 0.f;

    for (int kt = 0; kt < 64; ++kt) {
        const float4 av = *(const float4*)(arow + kt * 8);
        const float4 bv = *(const float4*)(wrow + (size_t)kt * 8 * 512);
        __syncthreads();
        As[ka + 0][lrow] = av.x;
        As[ka + 1][lrow] = av.y;
        As[ka + 2][lrow] = av.z;
        As[ka + 3][lrow] = av.w;
        *(float4*)&Bs[bk][bc] = bv;
        __syncthreads();
        #pragma unroll
        for (int k = 0; k < 8; ++k) {
            float4 a0 = *(const float4*)&As[k][ty * 4];
            float4 a1 = *(const float4*)&As[k][64 + ty * 4];
            float4 b0 = *(const float4*)&Bs[k][tx * 4];
            float4 b1 = *(const float4*)&Bs[k][64 + tx * 4];
            float aa[8] = {a0.x, a0.y, a0.z, a0.w, a1.x, a1.y, a1.z, a1.w};
            float bb[8] = {b0.x, b0.y, b0.z, b0.w, b1.x, b1.y, b1.z, b1.w};
            #pragma unroll
            for (int i = 0; i < 8; ++i)
                #pragma unroll
                for (int j = 0; j < 8; ++j)
                    acc[i][j] = fmaf(aa[i], bb[j], acc[i][j]);
        }
    }

    // epilogue: bias add, store, accumulate per-column sum / sumsq
    float bcol[8];
    #pragma unroll
    for (int j = 0; j < 8; ++j) {
        int lc = (j < 4) ? (tx * 4 + j) : (64 + tx * 4 + j - 4);
        bcol[j] = bias ? bias[(size_t)z * 512 + n0 + lc] : 0.f;
    }
    float vsum[8], vsq[8];
    #pragma unroll
    for (int j = 0; j < 8; ++j) { vsum[j] = 0.f; vsq[j] = 0.f; }

    #pragma unroll
    for (int i = 0; i < 8; ++i) {
        int row = m0 + ((i < 4) ? (ty * 4 + i) : (64 + ty * 4 + i - 4));
        float* yrow = Y + ((size_t)z * M + row) * 512 + n0;
        float v[8];
        #pragma unroll
        for (int j = 0; j < 8; ++j) {
            v[j] = acc[i][j] + bcol[j];
            vsum[j] += v[j];
            vsq[j]  += v[j] * v[j];
        }
        *(float4*)(yrow + tx * 4)      = make_float4(v[0], v[1], v[2], v[3]);
        *(float4*)(yrow + 64 + tx * 4) = make_float4(v[4], v[5], v[6], v[7]);
    }

    if (stats) {
        if (tid < 256) cstat[tid] = 0.f;
        __syncthreads();
        #pragma unroll
        for (int j = 0; j < 8; ++j) {
            int lc = (j < 4) ? (tx * 4 + j) : (64 + tx * 4 + j - 4);
            atomicAdd(&cstat[lc],       vsum[j]);
            atomicAdd(&cstat[128 + lc], vsq[j]);
        }
        __syncthreads();
        if (tid < 128) {
            atomicAdd(&stats[((size_t)z * 512 + n0 + tid) * 2],     cstat[tid]);
            atomicAdd(&stats[((size_t)z * 512 + n0 + tid) * 2 + 1], cstat[128 + tid]);
        }
    }
}

// ---------------- BN+ReLU on h (in place) + seq-mean ----------------
__global__ void bn_h_kernel(const float* __restrict__ gamma, const float* __restrict__ beta)
{
    const int bt = blockIdx.x;
    const int r  = blockIdx.y;
    const int c  = threadIdx.x;
    const float s1 = g_rstats[(r * 512 + c) * 2];
    const float s2 = g_rstats[(r * 512 + c) * 2 + 1];
    const float inv_n = 1.f / 21504.f;
    const float mean  = s1 * inv_n;
    const float var   = s2 * inv_n - mean * mean;
    const float rstd  = rsqrtf(var + EPSF);
    const float sc = gamma[r * 512 + c] * rstd;
    const float sh = beta[r * 512 + c] - mean * sc;
    size_t base = ((size_t)r * 21504 + (size_t)bt * 21) * 512 + c;
    float accv = 0.f;
    #pragma unroll
    for (int s = 0; s < 21; ++s) {
        float v = g_h[base + (size_t)s * 512];
        v = fmaxf(fmaf(v, sc, sh), 0.f);
        g_h[base + (size_t)s * 512] = v;
        accv += v;
    }
    g_hmean[((size_t)r * 1024 + bt) * 512 + c] = accv * (1.f / 21.f);
}

// ---------------- BN+ReLU on y + seq-mean -> f_v (no store of activated y) ----------------
__global__ void bn_y_kernel(const float* __restrict__ gamma, const float* __restrict__ beta)
{
    const int bt = blockIdx.x;
    const int n  = blockIdx.y;
    const int c  = threadIdx.x;
    const float s1 = g_cstats[(n * 512 + c) * 2];
    const float s2 = g_cstats[(n * 512 + c) * 2 + 1];
    const float inv_n = 1.f / 21504.f;
    const float mean  = s1 * inv_n;
    const float var   = s2 * inv_n - mean * mean;
    const float rstd  = rsqrtf(var + EPSF);
    const float sc = gamma[n * 512 + c] * rstd;
    const float sh = beta[n * 512 + c] - mean * sc;
    size_t base = ((size_t)n * 21504 + (size_t)bt * 21) * 512 + c;
    float accv = 0.f;
    #pragma unroll
    for (int s = 0; s < 21; ++s) {
        float v = g_y[base + (size_t)s * 512];
        accv += fmaxf(fmaf(v, sc, sh), 0.f);
    }
    g_fv[((size_t)bt * 12 + n) * 512 + c] = accv * (1.f / 21.f);
}

// ---------------- small prediction heads ----------------
__global__ void preds_kernel(const float* __restrict__ upW,  const float* __restrict__ upb,
                             const float* __restrict__ midW, const float* __restrict__ midb,
                             const float* __restrict__ d1W,  const float* __restrict__ d1b,
                             const float* __restrict__ d2W,  const float* __restrict__ d2b,
                             float* __restrict__ out)
{
    __shared__ float sm[4 * 512];
    const int bt = blockIdx.x;
    for (int i = threadIdx.x; i < 2048; i += blockDim.x)
        sm[i] = g_hmean[((size_t)(i >> 9) * 1024 + bt) * 512 + (i & 511)];
    __syncthreads();
    const int t = threadIdx.x;
    if (t < 42) {
        int r, j, nout;
        const float* Wp;
        const float* bp;
        float* op;
        if (t < 16)      { r = 0; j = t;      Wp = upW;  bp = upb;  op = out + (size_t)bt * 16;          nout = 16; }
        else if (t < 18) { r = 1; j = t - 16; Wp = midW; bp = midb; op = out + 16384 + (size_t)bt * 2;   nout = 2;  }
        else if (t < 26) { r = 2; j = t - 18; Wp = d1W;  bp = d1b;  op = out + 18432 + (size_t)bt * 8;   nout = 8;  }
        else             { r = 3; j = t - 26; Wp = d2W;  bp = d2b;  op = out + 26624 + (size_t)bt * 16;  nout = 16; }
        float accv = bp[j];
        const float* s = sm + r * 512;
        for (int c = 0; c < 512; ++c) accv += s[c] * Wp[c * nout + j];
        op[j] = accv;
    }
}

// ---------------- GAT: projections, attention, aggregation + residual ----------------
__global__ void gat_kernel(const float* __restrict__ adj_mask,
                           const float* __restrict__ al,
                           const float* __restrict__ ar)
{
    __shared__ float hs[12 * 512];
    __shared__ float alp[12], arp[12];
    __shared__ float att[144];
    const int bt = blockIdx.x;
    const float* hgb = g_hg + (size_t)bt * 12 * 512;
    for (int i = threadIdx.x; i < 6144; i += 256) hs[i] = hgb[i];
    __syncthreads();
    const int w = threadIdx.x >> 5, lane = threadIdx.x & 31;
    for (int d = w; d < 24; d += 8) {
        int node = d >> 1;
        const float* vec = (d & 1) ? ar : al;
        float s = 0.f;
        for (int c = lane; c < 512; c += 32) s += hs[node * 512 + c] * vec[c];
        #pragma unroll
        for (int o = 16; o; o >>= 1) s += __shfl_xor_sync(0xFFFFFFFFu, s, o);
        if (lane == 0) { if (d & 1) arp[node] = s; else alp[node] = s; }
    }
    __syncthreads();
    if (threadIdx.x < 144) {
        int i = threadIdx.x / 12, j = threadIdx.x % 12;
        float a = c_adj[threadIdx.x] * adj_mask[(size_t)bt * 144 + threadIdx.x] + (i == j ? 1.f : 0.f);
        float e = alp[i] + arp[j];
        e = (e > 0.f) ? e : 0.2f * e;
        att[threadIdx.x] = (a > 0.1f) ? e : -1e9f;
    }
    __syncthreads();
    if (threadIdx.x < 12) {
        int i = threadIdx.x;
        float mx = -1e30f;
        for (int j = 0; j < 12; ++j) mx = fmaxf(mx, att[i * 12 + j]);
        float tmp[12];
        float sum = 0.f;
        for (int j = 0; j < 12; ++j) { float ev = expf(att[i * 12 + j] - mx); tmp[j] = ev; sum += ev; }
        float invs = 1.f / sum;
        for (int j = 0; j < 12; ++j) att[i * 12 + j] = tmp[j] * invs;
    }
    __syncthreads();
    const float* fvb = g_fv + (size_t)bt * 12 * 512;
    float* gb = g_gat + (size_t)bt * 12 * 512;
    for (int idx = threadIdx.x; idx < 6144; idx += 256) {
        int n = idx >> 9, c = idx & 511;
        float s = fvb[idx];
        #pragma unroll
        for (int j = 0; j < 12; ++j) s += att[n * 12 + j] * hs[j * 512 + c];
        gb[idx] = s;
    }
}

// ---------------- depthwise temporal conv (k=5, pad=2) + BN statistics ----------------
__global__ void tconv_kernel(const float* __restrict__ W, const float* __restrict__ bias)
{
    const int bt = blockIdx.x;
    const int n  = blockIdx.y;
    const int b  = bt >> 5, t = bt & 31;
    const int c  = threadIdx.x;
    const float* wp = W + ((size_t)n * 512 + c) * 5;
    float v = bias[n * 512 + c];
    #pragma unroll
    for (int k = 0; k < 5; ++k) {
        int tt = t + k - 2;
        if (tt >= 0 && tt < 32)
            v += g_gat[(((size_t)(b * 32 + tt)) * 12 + n) * 512 + c] * wp[k];
    }
    g_v[((size_t)bt * 12 + n) * 512 + c] = v;

    // stats reduce (sum, sumsq) over the 512 channels of this (bt, n)
    float s = v, s2 = v * v;
    #pragma unroll
    for (int o = 16; o; o >>= 1) {
        s  += __shfl_xor_sync(0xFFFFFFFFu, s, o);
        s2 += __shfl_xor_sync(0xFFFFFFFFu, s2, o);
    }
    __shared__ float wsum[16], wsq[16];
    const int lane = c & 31, wrp = c >> 5;
    if (lane == 0) { wsum[wrp] = s; wsq[wrp] = s2; }
    __syncthreads();
    if (c == 0) {
        float a = 0.f, b2 = 0.f;
        #pragma unroll
        for (int i = 0; i < 16; ++i) { a += wsum[i]; b2 += wsq[i]; }
        atomicAdd(&g_tstats[n * 2],     a);
        atomicAdd(&g_tstats[n * 2 + 1], b2);
    }
}

// ---------------- final per-class BN + ReLU -> output ----------------
__global__ void tbn_kernel(const float* __restrict__ gamma, const float* __restrict__ beta,
                           float* __restrict__ out)
{
    const int bt = blockIdx.x;
    const int n  = blockIdx.y;
    const int c  = threadIdx.x;
    const float cnt = 1.f / (1024.f * 512.f);
    const float mean = g_tstats[n * 2] * cnt;
    const float var  = g_tstats[n * 2 + 1] * cnt - mean * mean;
    const float rstd = rsqrtf(var + EPSF);
    const float sc = gamma[n] * rstd;
    const float sh = beta[n] - mean * sc;
    size_t idx = ((size_t)bt * 12 + n) * 512 + c;
    out[43008 + idx] = fmaxf(fmaf(g_v[idx], sc, sh), 0.f);
}

// ---------------- launch ----------------
extern "C" void kernel_launch(void* const* d_in, const int* in_sizes, int n_in,
                              void* d_out, int out_size)
{
    const float* x            = (const float*)d_in[0];
    const float* adj_mask     = (const float*)d_in[1];
    const float* region_W     = (const float*)d_in[2];
    const float* region_b     = (const float*)d_in[3];
    const float* region_gamma = (const float*)d_in[4];
    const float* region_beta  = (const float*)d_in[5];
    const float* upfc_W  = (const float*)d_in[6];
    const float* upfc_b  = (const float*)d_in[7];
    const float* midfc_W = (const float*)d_in[8];
    const float* midfc_b = (const float*)d_in[9];
    const float* d1fc_W  = (const float*)d_in[10];
    const float* d1fc_b  = (const float*)d_in[11];
    const float* d2fc_W  = (const float*)d_in[12];
    const float* d2fc_b  = (const float*)d_in[13];
    const float* class_W     = (const float*)d_in[14];
    const float* class_b     = (const float*)d_in[15];
    const float* class_gamma = (const float*)d_in[16];
    const float* class_beta  = (const float*)d_in[17];
    const float* gat_W  = (const float*)d_in[18];
    const float* gat_al = (const float*)d_in[19];
    const float* gat_ar = (const float*)d_in[20];
    const float* tconv_W   = (const float*)d_in[21];
    const float* tconv_b   = (const float*)d_in[22];
    const float* tbn_gamma = (const float*)d_in[23];
    const float* tbn_beta  = (const float*)d_in[24];
    float* out = (float*)d_out;

    zero_stats_kernel<<<48, 256>>>();
    // region GEMMs: 4 x [21504, 512] = [21504, 512] @ [512, 512] (+bias, +stats)
    gemm_k<<<dim3(4, 168, 4), 256>>>(x, region_W, region_b, 21504, 0);
    bn_h_kernel<<<dim3(1024, 4), 512>>>(region_gamma, region_beta);
    preds_kernel<<<1024, 64>>>(upfc_W, upfc_b, midfc_W, midfc_b,
                               d1fc_W, d1fc_b, d2fc_W, d2fc_b, out);
    // class GEMMs: 12 x [21504, 512] @ [512, 512] (+bias, +stats)
    gemm_k<<<dim3(4, 168, 12), 256>>>(nullptr, class_W, class_b, 21504, 1);
    bn_y_kernel<<<dim3(1024, 12), 512>>>(class_gamma, class_beta);
    // GAT projection GEMM: [12288, 512] @ [512, 512]
    gemm_k<<<dim3(4, 96, 1), 256>>>(nullptr, gat_W, nullptr, 12288, 2);
    gat_kernel<<<1024, 256>>>(adj_mask, gat_al, gat_ar);
    tconv_kernel<<<dim3(1024, 12), 512>>>(tconv_W, tconv_b);
    tbn_kernel<<<dim3(1024, 12), 512>>>(tbn_gamma, tbn_beta, out);
}